// round 7
// baseline (speedup 1.0000x reference)
#include <cuda_runtime.h>
#include <cuda_bf16.h>
#include <cstdint>

// EmbeddingLoss via HMMA bf16 Gram, persistent CTAs + cp.async double buffer,
// algebraic epilogue: only !same pairs scored with max(s,0.5); same-pair and
// constant terms computed analytically from per-class sums.
// total = N * [ sum_{!same} w*max(s,0.5) - 0.5*sum_b(P^2-P) + sum_b(P - sum_l |u_l|^2/cnt^2) ]

namespace {
constexpr int NPIX  = 4096;
constexpr int CH    = 64;
constexpr int BATCH = 4;
constexpr int BM    = 128;
constexpr int TILES = NPIX / BM;                 // 32
constexpr int TRI   = TILES * (TILES + 1) / 2;   // 528
constexpr int NTILES = BATCH * TRI;              // 2112
constexpr int PGRID  = 296;                      // persistent blocks (2/SM)
constexpr int MAXT   = (NTILES + PGRID - 1) / PGRID;  // 8
constexpr int CONV_BLOCKS = BATCH * NPIX * CH / 4 / 256;  // 1024
constexpr int CLS_PER_B = 16;
constexpr int CLS_BLOCKS = BATCH * CLS_PER_B;    // 64
constexpr float MARGIN = 0.5f;
}

__device__ double   g_acc;
__device__ unsigned g_done;
__device__ float    g_pw[BATCH * NPIX];
__device__ int      g_cnt[BATCH * 16];
__device__ float    g_cls[BATCH * 16 * CH];      // zeroed at load; re-zeroed by finalize
__device__ __nv_bfloat16 g_ebf[BATCH * NPIX * CH];

__device__ __forceinline__ uint32_t smem_u32(const void* p) {
    uint32_t a;
    asm("{ .reg .u64 t; cvta.to.shared.u64 t, %1; cvt.u32.u64 %0, t; }"
        : "=r"(a) : "l"(p));
    return a;
}
__device__ __forceinline__ void ldsm_x4(uint32_t& r0, uint32_t& r1,
                                        uint32_t& r2, uint32_t& r3, uint32_t a) {
    asm volatile("ldmatrix.sync.aligned.m8n8.x4.shared.b16 {%0,%1,%2,%3}, [%4];"
                 : "=r"(r0), "=r"(r1), "=r"(r2), "=r"(r3) : "r"(a));
}
__device__ __forceinline__ void mma16816(float* d, const uint32_t* a,
                                         uint32_t b0, uint32_t b1) {
    asm volatile(
        "mma.sync.aligned.m16n8k16.row.col.f32.bf16.bf16.f32 "
        "{%0,%1,%2,%3}, {%4,%5,%6,%7}, {%8,%9}, {%0,%1,%2,%3};"
        : "+f"(d[0]), "+f"(d[1]), "+f"(d[2]), "+f"(d[3])
        : "r"(a[0]), "r"(a[1]), "r"(a[2]), "r"(a[3]), "r"(b0), "r"(b1));
}
__device__ __forceinline__ uint32_t sw_off(int R, int c) {
    return (uint32_t)(R * 128 + ((c ^ (R & 7)) << 4));
}
__device__ __forceinline__ void cp16(uint32_t s, const void* g) {
    asm volatile("cp.async.cg.shared.global [%0], [%1], 16;" :: "r"(s), "l"(g));
}

// ---------------- K1: conv + hist + class sums -------------------------------
__global__ __launch_bounds__(256) void prep_conv_kernel(const float* __restrict__ emb,
                                                        const int* __restrict__ lab) {
    const int bx = blockIdx.x, tid = threadIdx.x;
    if (bx < CONV_BLOCKS) {
        const int q = bx * 256 + tid;
        const int c4 = (q & 15) * 4;
        const int n  = (q >> 4) & (NPIX - 1);
        const float4 v = reinterpret_cast<const float4*>(emb)[q];
        const int chunk = c4 >> 3;
        const int dcol  = ((chunk ^ (n & 7)) << 3) + (c4 & 7);
        __nv_bfloat162* d2 = reinterpret_cast<__nv_bfloat162*>(
            g_ebf + ((size_t)(q >> 4)) * CH + dcol);
        d2[0] = __nv_bfloat162(__float2bfloat16(v.x), __float2bfloat16(v.y));
        d2[1] = __nv_bfloat162(__float2bfloat16(v.z), __float2bfloat16(v.w));
    } else if (bx < CONV_BLOCKS + BATCH) {
        __shared__ int hist[8][16];
        const int b = bx - CONV_BLOCKS;
        const int w = tid >> 5;
        if (tid < 128) hist[tid >> 4][tid & 15] = 0;
        if (b == 0 && tid == 0) { g_acc = 0.0; g_done = 0u; }
        __syncthreads();
        const int* L = lab + b * NPIX;
        for (int n = tid; n < NPIX; n += 256) atomicAdd(&hist[w][L[n] & 15], 1);
        __syncthreads();
        if (tid < 16) {
            int s = 0;
#pragma unroll
            for (int i = 0; i < 8; i++) s += hist[i][tid];
            hist[0][tid] = s;
            g_cnt[b * 16 + tid] = s;
        }
        __syncthreads();
        for (int n = tid; n < NPIX; n += 256)
            g_pw[b * NPIX + n] = 1.0f / (float)hist[0][L[n] & 15];
    } else {
        // per-class sums over a 256-row slice
        __shared__ float us[4][16][CH];   // 16KB
        __shared__ int   labs[256];
        const int cb = bx - CONV_BLOCKS - BATCH;
        const int b  = cb / CLS_PER_B;
        const int r0 = (cb % CLS_PER_B) * 256;
        for (int i = tid; i < 4 * 16 * CH; i += 256)
            (&us[0][0][0])[i] = 0.0f;
        labs[tid] = lab[b * NPIX + r0 + tid];
        __syncthreads();
        const int ch = tid & 63, g = tid >> 6;
        const float* Eb = emb + ((size_t)(b * NPIX + r0 + g * 64)) * CH + ch;
#pragma unroll 4
        for (int k = 0; k < 64; k++)
            us[g][labs[g * 64 + k] & 15][ch] += Eb[(size_t)k * CH];
        __syncthreads();
        for (int i = tid; i < 16 * CH; i += 256) {
            const float v = us[0][0][i] + us[1][0][i] + us[2][0][i] + us[3][0][i];
            if (v != 0.0f) atomicAdd(&g_cls[b * 16 * CH + i], v);
        }
    }
}

// ---------------- K2: persistent HMMA Gram + uniform 3-op epilogue ----------
__global__ __launch_bounds__(256, 2) void gram_kernel(const int* __restrict__ lab,
                                                      float* __restrict__ out) {
    __shared__ __align__(16) __nv_bfloat16 Asm[2][BM * CH];
    __shared__ __align__(16) __nv_bfloat16 Bsm[2][BM * CH];
    __shared__ int   lrow[2][BM], lcol[2][BM];
    __shared__ float prowf[2][BM], pcol[2][BM];  // prowf = (diag?1:2)*pw
    __shared__ int   tinfo[MAXT];
    __shared__ float red[8];
    __shared__ int   lastflag;
    __shared__ float sSum, sP[BATCH];

    const int tid = threadIdx.x;
    const int wid = tid >> 5;
    const int lid = tid & 31;
    const int wr  = wid & 1;
    const int wc  = wid >> 1;
    const int bid = blockIdx.x;

    const uint32_t aS[2] = { smem_u32(Asm[0]), smem_u32(Asm[1]) };
    const uint32_t bS[2] = { smem_u32(Bsm[0]), smem_u32(Bsm[1]) };

    const int nt = (NTILES - bid + PGRID - 1) / PGRID;

    // decode all of this block's tiles once (thread 0)
    if (tid == 0) {
        lastflag = 0;
        for (int k = 0; k < nt; k++) {
            const int idx = bid + k * PGRID;
            const int b = idx / TRI;
            int t = idx - b * TRI;
            int u = 0;
            while (t >= TILES - u) { t -= TILES - u; u++; }
            tinfo[k] = (b << 12) | (u << 6) | (u + t);
        }
    }
    if (tid < BATCH) sP[tid] = 0.0f;
    if (tid == 1) sSum = 0.0f;
    __syncthreads();

    auto issue = [&](int k, int par) {
        const int inf = tinfo[k];
        const int b = inf >> 12, ti = (inf >> 6) & 63, tj = inf & 63;
        const int row0 = ti * BM, col0 = tj * BM;
        const char* srcA = (const char*)(g_ebf + ((size_t)(b * NPIX + row0)) * CH);
        const char* srcB = (const char*)(g_ebf + ((size_t)(b * NPIX + col0)) * CH);
#pragma unroll
        for (int p = 0; p < 4; p++) {
            const int o = (tid + 256 * p) * 16;
            cp16(aS[par] + o, srcA + o);
            cp16(bS[par] + o, srcB + o);
        }
        if (tid < BM) {
            lrow[par][tid]  = lab[b * NPIX + row0 + tid];
            prowf[par][tid] = (ti == tj ? 1.0f : 2.0f) * g_pw[b * NPIX + row0 + tid];
        } else {
            const int u = tid - BM;
            lcol[par][u] = lab[b * NPIX + col0 + u];
            pcol[par][u] = g_pw[b * NPIX + col0 + u];
        }
        asm volatile("cp.async.commit_group;" ::: "memory");
    };

    float tsum = 0.0f;
    issue(0, 0);

    int par = 0;
    for (int k = 0; k < nt; k++) {
        const bool has_next = (k + 1 < nt);
        if (has_next) issue(k + 1, par ^ 1);
        if (has_next) asm volatile("cp.async.wait_group 1;" ::: "memory");
        else          asm volatile("cp.async.wait_group 0;" ::: "memory");
        __syncthreads();

        const uint32_t a_base = aS[par];
        const uint32_t b_base = bS[par];

        float acc[4][4][4];
#pragma unroll
        for (int i = 0; i < 4; i++)
#pragma unroll
            for (int j = 0; j < 4; j++)
#pragma unroll
                for (int e = 0; e < 4; e++) acc[i][j][e] = 0.0f;

        const int aR = 64 * wr + (lid & 15);
        const int bR = 32 * wc + (lid & 15);
        const int hi = lid >> 4;

#pragma unroll
        for (int ks = 0; ks < 4; ks++) {
            const int ck = ks * 2 + hi;
            uint32_t a[4][4];
#pragma unroll
            for (int i = 0; i < 4; i++) {
                const int R = aR + 16 * i;
                ldsm_x4(a[i][0], a[i][1], a[i][2], a[i][3], a_base + sw_off(R, ck));
            }
            uint32_t bb[2][4];
#pragma unroll
            for (int p = 0; p < 2; p++) {
                const int R = bR + 16 * p;
                ldsm_x4(bb[p][0], bb[p][1], bb[p][2], bb[p][3], b_base + sw_off(R, ck));
            }
#pragma unroll
            for (int i = 0; i < 4; i++)
#pragma unroll
                for (int j = 0; j < 4; j++)
                    mma16816(acc[i][j], a[i], bb[j >> 1][j & 1], bb[j >> 1][(j & 1) + 2]);
        }

        // -------- uniform epilogue: !same pairs only, max(s,0.5) ------------
        const int gr = lid >> 2;
        const int qc = (lid & 3) * 2;
        int   lcv[8];
        float pcv[8];
#pragma unroll
        for (int j = 0; j < 4; j++) {
            const int cl = 32 * wc + 8 * j + qc;
            lcv[2 * j]     = lcol[par][cl];
            lcv[2 * j + 1] = lcol[par][cl + 1];
            pcv[2 * j]     = pcol[par][cl];
            pcv[2 * j + 1] = pcol[par][cl + 1];
        }
#pragma unroll
        for (int i = 0; i < 4; i++) {
            const int rl0 = 64 * wr + 16 * i + gr, rl1 = rl0 + 8;
            const int ln0 = lrow[par][rl0], ln1 = lrow[par][rl1];
            float rs0 = 0.0f, rs1 = 0.0f;
#pragma unroll
            for (int j = 0; j < 4; j++) {
                const float m0 = fmaxf(acc[i][j][0], MARGIN);
                const float m1 = fmaxf(acc[i][j][1], MARGIN);
                const float m2 = fmaxf(acc[i][j][2], MARGIN);
                const float m3 = fmaxf(acc[i][j][3], MARGIN);
                if (ln0 != lcv[2 * j])     rs0 = fmaf(m0, pcv[2 * j],     rs0);
                if (ln0 != lcv[2 * j + 1]) rs0 = fmaf(m1, pcv[2 * j + 1], rs0);
                if (ln1 != lcv[2 * j])     rs1 = fmaf(m2, pcv[2 * j],     rs1);
                if (ln1 != lcv[2 * j + 1]) rs1 = fmaf(m3, pcv[2 * j + 1], rs1);
            }
            tsum = fmaf(rs0, prowf[par][rl0], tsum);
            tsum = fmaf(rs1, prowf[par][rl1], tsum);
        }
        __syncthreads();
        par ^= 1;
    }

    // -------- one reduction + atomic per block; last block finalizes --------
#pragma unroll
    for (int o = 16; o > 0; o >>= 1)
        tsum += __shfl_xor_sync(0xffffffffu, tsum, o);
    if (lid == 0) red[wid] = tsum;
    __syncthreads();
    if (tid == 0) {
        float bsum = 0.0f;
#pragma unroll
        for (int wv = 0; wv < 8; wv++) bsum += red[wv];
        atomicAdd(&g_acc, (double)bsum);
        __threadfence();
        const unsigned done = atomicAdd(&g_done, 1u);
        if (done == (unsigned)(PGRID - 1)) lastflag = 1;
    }
    __syncthreads();

    if (lastflag) {
        __threadfence();
        if (tid < BATCH * 16) {
            const int bb_ = tid >> 4;
            const int cnt = g_cnt[tid];
            if (cnt > 0) {
                float dot = 0.0f;
                const float* u = g_cls + tid * CH;
#pragma unroll 8
                for (int c = 0; c < CH; c++) dot = fmaf(u[c], u[c], dot);
                const float inv = 1.0f / ((float)cnt * (float)cnt);
                atomicAdd(&sSum, 1.0f - dot * inv);
                atomicAdd(&sP[bb_], 1.0f);
            }
        }
        __syncthreads();
        if (tid == 0) {
            double extra = (double)sSum;
            for (int bb_ = 0; bb_ < BATCH; bb_++) {
                const double P = (double)sP[bb_];
                extra -= 0.5 * (P * P - P);
            }
            out[0] = (float)((*((volatile double*)&g_acc) + extra) * (double)NPIX);
        }
        for (int i = tid; i < BATCH * 16 * CH; i += 256) g_cls[i] = 0.0f;
    }
}

extern "C" void kernel_launch(void* const* d_in, const int* in_sizes, int n_in,
                              void* d_out, int out_size) {
    const float* emb = (const float*)d_in[0];
    const int*   lab = (const int*)d_in[1];
    float* out = (float*)d_out;

    prep_conv_kernel<<<CONV_BLOCKS + BATCH + CLS_BLOCKS, 256>>>(emb, lab);
    gram_kernel<<<PGRID, 256>>>(lab, out);
}